// round 1
// baseline (speedup 1.0000x reference)
#include <cuda_runtime.h>
#include <stdint.h>

// Problem constants (fixed shapes per reference)
#define TT 4
#define NN 8192
#define DD 1024
#define NE 8
#define FF 512
#define KTOP 2

#define TM 64          // tokens per tile
#define TN 64          // f (or d) per tile
#define BK 16          // K chunk
#define NSLOT   (NN * KTOP)            // 16384
#define MAXSLOT (NSLOT + NE * TM)      // 16896 (padded)
#define NTILE   (MAXSLOT / TM)         // 264

#define BETA 0.9f
#define THRESH 1.0f

// Scratch (device globals: no allocation allowed)
__device__ float g_h[(size_t)TT * MAXSLOT * FF];   // spikes from up-proj, fp32 0/1
__device__ int   g_tok[MAXSLOT];
__device__ float g_gate[MAXSLOT];
__device__ int   g_exp[MAXSLOT];
__device__ int   g_cnt[NE];
__device__ int   g_cur[NE];
__device__ int   g_off[NE + 1];

// ---------------- routing ----------------

__global__ void k_zero(float4* out, int n4) {
    int stride = gridDim.x * blockDim.x;
    for (int i = blockIdx.x * blockDim.x + threadIdx.x; i < n4; i += stride)
        out[i] = make_float4(0.f, 0.f, 0.f, 0.f);
}

__global__ void k_init() {
    int i = threadIdx.x;
    if (i < NE) g_cnt[i] = 0;
}

__global__ void k_count(const int* __restrict__ idx) {
    int i = blockIdx.x * blockDim.x + threadIdx.x;
    if (i < NSLOT) atomicAdd(&g_cnt[idx[i]], 1);
}

__global__ void k_scan() {
    if (threadIdx.x == 0 && blockIdx.x == 0) {
        int off = 0;
        for (int e = 0; e < NE; e++) {
            g_off[e] = off;
            g_cur[e] = off;
            off += ((g_cnt[e] + TM - 1) / TM) * TM;
        }
        g_off[NE] = off;
    }
}

__global__ void k_padinit() {
    int s = blockIdx.x * blockDim.x + threadIdx.x;
    if (s < MAXSLOT) {
        g_tok[s]  = -1;
        g_gate[s] = 0.f;
        int e = 0;
        #pragma unroll
        for (int q = 0; q < NE; q++)
            if (s >= g_off[q]) e = q;
        g_exp[s] = e;
    }
}

__global__ void k_fill(const int* __restrict__ idx, const float* __restrict__ wts) {
    int i = blockIdx.x * blockDim.x + threadIdx.x;
    if (i < NSLOT) {
        int e = idx[i];
        int p = atomicAdd(&g_cur[e], 1);
        g_tok[p]  = i >> 1;     // n = i / TOPK
        g_gate[p] = wts[i];
    }
}

// ---------------- up-proj + LIF -> spikes ----------------
// grid: (NTILE, FF/TN). Block: 256 threads, tile TM tokens x TN f, 4 time accums.

__global__ __launch_bounds__(256, 2)
void k_up(const float* __restrict__ x, const float* __restrict__ upw) {
    const int sbase = blockIdx.x * TM;
    if (sbase >= g_off[NE]) return;
    const int e     = g_exp[sbase];
    const int fbase = blockIdx.y * TN;

    __shared__ float sx[TT][BK][TM + 4];
    __shared__ float sw[BK][TN + 4];

    const int tid = threadIdx.x;
    const int tx = tid & 15, ty = tid >> 4;
    const int tok0 = ty * 4, f0 = tx * 4;

    float acc[TT][4][4];
    #pragma unroll
    for (int t = 0; t < TT; t++)
        #pragma unroll
        for (int i = 0; i < 4; i++)
            #pragma unroll
            for (int j = 0; j < 4; j++)
                acc[t][i][j] = 0.f;

    // loader mapping: 256 threads -> 64 rows x 4 float4s
    const int l_row = tid >> 2;   // 0..63
    const int l_kq  = tid & 3;    // 0..3
    const int my_tok = g_tok[sbase + l_row];
    const float* xbase = x + (size_t)my_tok * DD + l_kq * 4;                       // guard deref
    const float* wrow  = upw + ((size_t)e * FF + (fbase + l_row)) * DD + l_kq * 4;

    for (int k0 = 0; k0 < DD; k0 += BK) {
        __syncthreads();
        #pragma unroll
        for (int t = 0; t < TT; t++) {
            float4 v = make_float4(0.f, 0.f, 0.f, 0.f);
            if (my_tok >= 0)
                v = *(const float4*)(xbase + (size_t)t * NN * DD + k0);
            sx[t][l_kq * 4 + 0][l_row] = v.x;
            sx[t][l_kq * 4 + 1][l_row] = v.y;
            sx[t][l_kq * 4 + 2][l_row] = v.z;
            sx[t][l_kq * 4 + 3][l_row] = v.w;
        }
        {
            float4 v = *(const float4*)(wrow + k0);
            sw[l_kq * 4 + 0][l_row] = v.x;
            sw[l_kq * 4 + 1][l_row] = v.y;
            sw[l_kq * 4 + 2][l_row] = v.z;
            sw[l_kq * 4 + 3][l_row] = v.w;
        }
        __syncthreads();

        #pragma unroll
        for (int k = 0; k < BK; k++) {
            float4 b = *(const float4*)&sw[k][f0];
            float bv[4] = {b.x, b.y, b.z, b.w};
            #pragma unroll
            for (int t = 0; t < TT; t++) {
                float4 a = *(const float4*)&sx[t][k][tok0];
                float av[4] = {a.x, a.y, a.z, a.w};
                #pragma unroll
                for (int i = 0; i < 4; i++)
                    #pragma unroll
                    for (int j = 0; j < 4; j++)
                        acc[t][i][j] += av[i] * bv[j];
            }
        }
    }

    // LIF over time per (token, f), store spikes (fp32 0/1)
    #pragma unroll
    for (int i = 0; i < 4; i++) {
        float m0 = 0.f, m1 = 0.f, m2 = 0.f, m3 = 0.f;
        const int slot = sbase + tok0 + i;
        #pragma unroll
        for (int t = 0; t < TT; t++) {
            m0 = BETA * m0 + acc[t][i][0];
            m1 = BETA * m1 + acc[t][i][1];
            m2 = BETA * m2 + acc[t][i][2];
            m3 = BETA * m3 + acc[t][i][3];
            float s0 = (m0 > THRESH) ? 1.f : 0.f;
            float s1 = (m1 > THRESH) ? 1.f : 0.f;
            float s2 = (m2 > THRESH) ? 1.f : 0.f;
            float s3 = (m3 > THRESH) ? 1.f : 0.f;
            m0 -= s0 * THRESH; m1 -= s1 * THRESH; m2 -= s2 * THRESH; m3 -= s3 * THRESH;
            *(float4*)&g_h[((size_t)t * MAXSLOT + slot) * FF + fbase + f0] =
                make_float4(s0, s1, s2, s3);
        }
    }
}

// ---------------- down-proj + LIF + gated scatter ----------------
// grid: (NTILE, DD/TN). K = FF = 512.

__global__ __launch_bounds__(256, 2)
void k_down(const float* __restrict__ dww, float* __restrict__ out) {
    const int sbase = blockIdx.x * TM;
    if (sbase >= g_off[NE]) return;
    const int e     = g_exp[sbase];
    const int dbase = blockIdx.y * TN;

    __shared__ float sh[TT][BK][TM + 4];
    __shared__ float sw[BK][TN + 4];

    const int tid = threadIdx.x;
    const int tx = tid & 15, ty = tid >> 4;
    const int tok0 = ty * 4, d0 = tx * 4;

    float acc[TT][4][4];
    #pragma unroll
    for (int t = 0; t < TT; t++)
        #pragma unroll
        for (int i = 0; i < 4; i++)
            #pragma unroll
            for (int j = 0; j < 4; j++)
                acc[t][i][j] = 0.f;

    const int l_row = tid >> 2;
    const int l_kq  = tid & 3;
    const float* hbase = g_h + (size_t)(sbase + l_row) * FF + l_kq * 4;
    const float* wrow  = dww + ((size_t)e * DD + (dbase + l_row)) * FF + l_kq * 4;

    for (int k0 = 0; k0 < FF; k0 += BK) {
        __syncthreads();
        #pragma unroll
        for (int t = 0; t < TT; t++) {
            float4 v = *(const float4*)(hbase + (size_t)t * MAXSLOT * FF + k0);
            sh[t][l_kq * 4 + 0][l_row] = v.x;
            sh[t][l_kq * 4 + 1][l_row] = v.y;
            sh[t][l_kq * 4 + 2][l_row] = v.z;
            sh[t][l_kq * 4 + 3][l_row] = v.w;
        }
        {
            float4 v = *(const float4*)(wrow + k0);
            sw[l_kq * 4 + 0][l_row] = v.x;
            sw[l_kq * 4 + 1][l_row] = v.y;
            sw[l_kq * 4 + 2][l_row] = v.z;
            sw[l_kq * 4 + 3][l_row] = v.w;
        }
        __syncthreads();

        #pragma unroll
        for (int k = 0; k < BK; k++) {
            float4 b = *(const float4*)&sw[k][d0];
            float bv[4] = {b.x, b.y, b.z, b.w};
            #pragma unroll
            for (int t = 0; t < TT; t++) {
                float4 a = *(const float4*)&sh[t][k][tok0];
                float av[4] = {a.x, a.y, a.z, a.w};
                #pragma unroll
                for (int i = 0; i < 4; i++)
                    #pragma unroll
                    for (int j = 0; j < 4; j++)
                        acc[t][i][j] += av[i] * bv[j];
            }
        }
    }

    // LIF over time, scatter gated spikes into out (atomic; at most 2 experts/token)
    #pragma unroll
    for (int i = 0; i < 4; i++) {
        const int slot = sbase + tok0 + i;
        const int tok  = g_tok[slot];
        if (tok < 0) continue;
        const float gate = g_gate[slot];
        float m0 = 0.f, m1 = 0.f, m2 = 0.f, m3 = 0.f;
        #pragma unroll
        for (int t = 0; t < TT; t++) {
            m0 = BETA * m0 + acc[t][i][0];
            m1 = BETA * m1 + acc[t][i][1];
            m2 = BETA * m2 + acc[t][i][2];
            m3 = BETA * m3 + acc[t][i][3];
            bool s0 = m0 > THRESH, s1 = m1 > THRESH, s2 = m2 > THRESH, s3 = m3 > THRESH;
            if (s0) m0 -= THRESH;
            if (s1) m1 -= THRESH;
            if (s2) m2 -= THRESH;
            if (s3) m3 -= THRESH;
            float* op = out + ((size_t)t * NN + tok) * DD + dbase + d0;
            if (s0) atomicAdd(op + 0, gate);
            if (s1) atomicAdd(op + 1, gate);
            if (s2) atomicAdd(op + 2, gate);
            if (s3) atomicAdd(op + 3, gate);
        }
    }
}

// ---------------- launch ----------------

extern "C" void kernel_launch(void* const* d_in, const int* in_sizes, int n_in,
                              void* d_out, int out_size) {
    const float* x    = (const float*)d_in[0];   // (T, N, D) f32
    const int*   idx  = (const int*)d_in[1];     // (N, TOPK) i32
    const float* wts  = (const float*)d_in[2];   // (N, TOPK) f32
    const float* upw  = (const float*)d_in[3];   // (E, EF, D) f32
    const float* dww  = (const float*)d_in[4];   // (E, D, EF) f32
    float* out = (float*)d_out;                  // (T, N, D) f32

    (void)in_sizes; (void)n_in; (void)out_size;

    // zero output (poisoned by harness)
    k_zero<<<4096, 256>>>((float4*)out, TT * NN * DD / 4);

    // routing
    k_init<<<1, 32>>>();
    k_count<<<(NSLOT + 255) / 256, 256>>>(idx);
    k_scan<<<1, 32>>>();
    k_padinit<<<(MAXSLOT + 255) / 256, 256>>>();
    k_fill<<<(NSLOT + 255) / 256, 256>>>(idx, wts);

    // up-proj + LIF
    k_up<<<dim3(NTILE, FF / TN), 256>>>(x, upw);

    // down-proj + LIF + combine
    k_down<<<dim3(NTILE, DD / TN), 256>>>(dww, out);
}

// round 2
// speedup vs baseline: 1.0735x; 1.0735x over previous
#include <cuda_runtime.h>
#include <stdint.h>

// Problem constants (fixed shapes per reference)
#define TT 4
#define NN 8192
#define DD 1024
#define NE 8
#define FF 512
#define KTOP 2

#define TM 64          // tokens per tile
#define TNW 128        // f (or d) per tile
#define BK 16          // K chunk
#define NSLOT   (NN * KTOP)            // 16384
#define MAXSLOT (NSLOT + NE * TM)      // 16896 (padded)
#define NTILE   (MAXSLOT / TM)         // 264

#define BETA 0.9f
#define THRESH 1.0f

// Scratch (device globals: no allocation allowed)
__device__ float g_h[(size_t)TT * MAXSLOT * FF];   // spikes from up-proj, fp32 0/1
__device__ int   g_tok[MAXSLOT];
__device__ float g_gate[MAXSLOT];
__device__ int   g_exp[MAXSLOT];
__device__ int   g_cnt[NE];
__device__ int   g_cur[NE];
__device__ int   g_off[NE + 1];

// ---------------- f32x2 helpers ----------------

__device__ __forceinline__ unsigned long long ffma2(unsigned long long a,
                                                    unsigned long long b,
                                                    unsigned long long c) {
    unsigned long long d;
    asm("fma.rn.f32x2 %0, %1, %2, %3;" : "=l"(d) : "l"(a), "l"(b), "l"(c));
    return d;
}

__device__ __forceinline__ unsigned long long packdup(float v) {
    unsigned long long r;
    asm("mov.b64 %0, {%1, %1};" : "=l"(r) : "f"(v));
    return r;
}

__device__ __forceinline__ void unpack2(unsigned long long v, float& lo, float& hi) {
    asm("mov.b64 {%0, %1}, %2;" : "=f"(lo), "=f"(hi) : "l"(v));
}

// ---------------- routing ----------------

__global__ void k_zero(float4* out, int n4) {
    int stride = gridDim.x * blockDim.x;
    for (int i = blockIdx.x * blockDim.x + threadIdx.x; i < n4; i += stride)
        out[i] = make_float4(0.f, 0.f, 0.f, 0.f);
}

__global__ void k_init() {
    int i = threadIdx.x;
    if (i < NE) g_cnt[i] = 0;
}

__global__ void k_count(const int* __restrict__ idx) {
    int i = blockIdx.x * blockDim.x + threadIdx.x;
    if (i < NSLOT) atomicAdd(&g_cnt[idx[i]], 1);
}

__global__ void k_scan() {
    if (threadIdx.x == 0 && blockIdx.x == 0) {
        int off = 0;
        for (int e = 0; e < NE; e++) {
            g_off[e] = off;
            g_cur[e] = off;
            off += ((g_cnt[e] + TM - 1) / TM) * TM;
        }
        g_off[NE] = off;
    }
}

__global__ void k_padinit() {
    int s = blockIdx.x * blockDim.x + threadIdx.x;
    if (s < MAXSLOT) {
        g_tok[s]  = -1;
        g_gate[s] = 0.f;
        int e = 0;
        #pragma unroll
        for (int q = 0; q < NE; q++)
            if (s >= g_off[q]) e = q;
        g_exp[s] = e;
    }
}

__global__ void k_fill(const int* __restrict__ idx, const float* __restrict__ wts) {
    int i = blockIdx.x * blockDim.x + threadIdx.x;
    if (i < NSLOT) {
        int e = idx[i];
        int p = atomicAdd(&g_cur[e], 1);
        g_tok[p]  = i >> 1;     // n = i / TOPK
        g_gate[p] = wts[i];
    }
}

// ---------------- up-proj + LIF -> spikes ----------------
// grid: (NTILE, FF/TNW). Block: 256 threads. Tile: TM(64) tokens x TNW(128) f.
// Thread tile: 4 tokens (2 f32x2 pairs) x 8 f x 4 t, f32x2 packed FFMA.

__global__ __launch_bounds__(256, 1)
void k_up(const float* __restrict__ x, const float* __restrict__ upw) {
    const int sbase = blockIdx.x * TM;
    if (sbase >= g_off[NE]) return;
    const int e     = g_exp[sbase];
    const int fbase = blockIdx.y * TNW;

    __shared__ float sx[TT][BK][TM + 4];
    __shared__ float sw[BK][TNW + 4];

    const int tid = threadIdx.x;
    const int tx = tid & 15, ty = tid >> 4;
    const int tok0 = ty * 4;
    const int f0A = tx * 4;         // f columns f0A..f0A+3
    const int f0B = 64 + tx * 4;    // f columns f0B..f0B+3

    unsigned long long acc[TT][2][8];
    #pragma unroll
    for (int t = 0; t < TT; t++)
        #pragma unroll
        for (int p = 0; p < 2; p++)
            #pragma unroll
            for (int j = 0; j < 8; j++)
                acc[t][p][j] = 0ULL;

    // x loader: 256 threads -> 64 rows x 4 float4 (per t)
    const int l_row = tid >> 2;   // 0..63
    const int l_kq  = tid & 3;    // 0..3
    const int my_tok = g_tok[sbase + l_row];
    const float* xbase = x + (size_t)my_tok * DD + l_kq * 4;

    // w loader: 256 threads -> 128 rows x 2 float4
    const int w_row = tid >> 1;           // 0..127
    const int w_k   = (tid & 1) * 8;      // 0 or 8
    const float* wrow = upw + ((size_t)e * FF + (fbase + w_row)) * DD + w_k;

    for (int k0 = 0; k0 < DD; k0 += BK) {
        __syncthreads();
        #pragma unroll
        for (int t = 0; t < TT; t++) {
            float4 v = make_float4(0.f, 0.f, 0.f, 0.f);
            if (my_tok >= 0)
                v = *(const float4*)(xbase + (size_t)t * NN * DD + k0);
            sx[t][l_kq * 4 + 0][l_row] = v.x;
            sx[t][l_kq * 4 + 1][l_row] = v.y;
            sx[t][l_kq * 4 + 2][l_row] = v.z;
            sx[t][l_kq * 4 + 3][l_row] = v.w;
        }
        {
            float4 v0 = *(const float4*)(wrow + k0);
            float4 v1 = *(const float4*)(wrow + k0 + 4);
            sw[w_k + 0][w_row] = v0.x;
            sw[w_k + 1][w_row] = v0.y;
            sw[w_k + 2][w_row] = v0.z;
            sw[w_k + 3][w_row] = v0.w;
            sw[w_k + 4][w_row] = v1.x;
            sw[w_k + 5][w_row] = v1.y;
            sw[w_k + 6][w_row] = v1.z;
            sw[w_k + 7][w_row] = v1.w;
        }
        __syncthreads();

        #pragma unroll
        for (int k = 0; k < BK; k++) {
            float4 bA = *(const float4*)&sw[k][f0A];
            float4 bB = *(const float4*)&sw[k][f0B];
            unsigned long long bb[8];
            bb[0] = packdup(bA.x); bb[1] = packdup(bA.y);
            bb[2] = packdup(bA.z); bb[3] = packdup(bA.w);
            bb[4] = packdup(bB.x); bb[5] = packdup(bB.y);
            bb[6] = packdup(bB.z); bb[7] = packdup(bB.w);
            #pragma unroll
            for (int t = 0; t < TT; t++) {
                ulonglong2 av = *(const ulonglong2*)&sx[t][k][tok0];
                #pragma unroll
                for (int j = 0; j < 8; j++) {
                    acc[t][0][j] = ffma2(av.x, bb[j], acc[t][0][j]);
                    acc[t][1][j] = ffma2(av.y, bb[j], acc[t][1][j]);
                }
            }
        }
    }

    // LIF over time per (token, f), store spikes (fp32 0/1)
    #pragma unroll
    for (int p = 0; p < 2; p++) {
        #pragma unroll
        for (int l = 0; l < 2; l++) {
            const int slot = sbase + tok0 + p * 2 + l;
            float m[8];
            #pragma unroll
            for (int j = 0; j < 8; j++) m[j] = 0.f;
            #pragma unroll
            for (int t = 0; t < TT; t++) {
                float s[8];
                #pragma unroll
                for (int j = 0; j < 8; j++) {
                    float lo, hi;
                    unpack2(acc[t][p][j], lo, hi);
                    float v = l ? hi : lo;
                    m[j] = BETA * m[j] + v;
                    s[j] = (m[j] > THRESH) ? 1.f : 0.f;
                    m[j] -= s[j] * THRESH;
                }
                float* dst = &g_h[((size_t)t * MAXSLOT + slot) * FF + fbase];
                *(float4*)(dst + f0A) = make_float4(s[0], s[1], s[2], s[3]);
                *(float4*)(dst + f0B) = make_float4(s[4], s[5], s[6], s[7]);
            }
        }
    }
}

// ---------------- down-proj + LIF + gated scatter ----------------
// grid: (NTILE, DD/TNW). K = FF = 512.

__global__ __launch_bounds__(256, 1)
void k_down(const float* __restrict__ dww, float* __restrict__ out) {
    const int sbase = blockIdx.x * TM;
    if (sbase >= g_off[NE]) return;
    const int e     = g_exp[sbase];
    const int dbase = blockIdx.y * TNW;

    __shared__ float sh[TT][BK][TM + 4];
    __shared__ float sw[BK][TNW + 4];

    const int tid = threadIdx.x;
    const int tx = tid & 15, ty = tid >> 4;
    const int tok0 = ty * 4;
    const int f0A = tx * 4;
    const int f0B = 64 + tx * 4;

    unsigned long long acc[TT][2][8];
    #pragma unroll
    for (int t = 0; t < TT; t++)
        #pragma unroll
        for (int p = 0; p < 2; p++)
            #pragma unroll
            for (int j = 0; j < 8; j++)
                acc[t][p][j] = 0ULL;

    const int l_row = tid >> 2;
    const int l_kq  = tid & 3;
    const float* hbase = g_h + (size_t)(sbase + l_row) * FF + l_kq * 4;

    const int w_row = tid >> 1;
    const int w_k   = (tid & 1) * 8;
    const float* wrow = dww + ((size_t)e * DD + (dbase + w_row)) * FF + w_k;

    for (int k0 = 0; k0 < FF; k0 += BK) {
        __syncthreads();
        #pragma unroll
        for (int t = 0; t < TT; t++) {
            float4 v = *(const float4*)(hbase + (size_t)t * MAXSLOT * FF + k0);
            sh[t][l_kq * 4 + 0][l_row] = v.x;
            sh[t][l_kq * 4 + 1][l_row] = v.y;
            sh[t][l_kq * 4 + 2][l_row] = v.z;
            sh[t][l_kq * 4 + 3][l_row] = v.w;
        }
        {
            float4 v0 = *(const float4*)(wrow + k0);
            float4 v1 = *(const float4*)(wrow + k0 + 4);
            sw[w_k + 0][w_row] = v0.x;
            sw[w_k + 1][w_row] = v0.y;
            sw[w_k + 2][w_row] = v0.z;
            sw[w_k + 3][w_row] = v0.w;
            sw[w_k + 4][w_row] = v1.x;
            sw[w_k + 5][w_row] = v1.y;
            sw[w_k + 6][w_row] = v1.z;
            sw[w_k + 7][w_row] = v1.w;
        }
        __syncthreads();

        #pragma unroll
        for (int k = 0; k < BK; k++) {
            float4 bA = *(const float4*)&sw[k][f0A];
            float4 bB = *(const float4*)&sw[k][f0B];
            unsigned long long bb[8];
            bb[0] = packdup(bA.x); bb[1] = packdup(bA.y);
            bb[2] = packdup(bA.z); bb[3] = packdup(bA.w);
            bb[4] = packdup(bB.x); bb[5] = packdup(bB.y);
            bb[6] = packdup(bB.z); bb[7] = packdup(bB.w);
            #pragma unroll
            for (int t = 0; t < TT; t++) {
                ulonglong2 av = *(const ulonglong2*)&sh[t][k][tok0];
                #pragma unroll
                for (int j = 0; j < 8; j++) {
                    acc[t][0][j] = ffma2(av.x, bb[j], acc[t][0][j]);
                    acc[t][1][j] = ffma2(av.y, bb[j], acc[t][1][j]);
                }
            }
        }
    }

    // LIF over time, scatter gated spikes into out (atomic; at most 2 experts/token)
    #pragma unroll
    for (int p = 0; p < 2; p++) {
        #pragma unroll
        for (int l = 0; l < 2; l++) {
            const int slot = sbase + tok0 + p * 2 + l;
            const int tok  = g_tok[slot];
            if (tok < 0) continue;
            const float gate = g_gate[slot];
            float m[8];
            #pragma unroll
            for (int j = 0; j < 8; j++) m[j] = 0.f;
            #pragma unroll
            for (int t = 0; t < TT; t++) {
                float* op = out + ((size_t)t * NN + tok) * DD + dbase;
                #pragma unroll
                for (int j = 0; j < 8; j++) {
                    float lo, hi;
                    unpack2(acc[t][p][j], lo, hi);
                    float v = l ? hi : lo;
                    m[j] = BETA * m[j] + v;
                    if (m[j] > THRESH) {
                        m[j] -= THRESH;
                        int col = (j < 4) ? (f0A + j) : (f0B + j - 4);
                        atomicAdd(op + col, gate);
                    }
                }
            }
        }
    }
}

// ---------------- launch ----------------

extern "C" void kernel_launch(void* const* d_in, const int* in_sizes, int n_in,
                              void* d_out, int out_size) {
    const float* x    = (const float*)d_in[0];   // (T, N, D) f32
    const int*   idx  = (const int*)d_in[1];     // (N, TOPK) i32
    const float* wts  = (const float*)d_in[2];   // (N, TOPK) f32
    const float* upw  = (const float*)d_in[3];   // (E, EF, D) f32
    const float* dww  = (const float*)d_in[4];   // (E, D, EF) f32
    float* out = (float*)d_out;                  // (T, N, D) f32

    (void)in_sizes; (void)n_in; (void)out_size;

    // zero output (poisoned by harness)
    k_zero<<<4096, 256>>>((float4*)out, TT * NN * DD / 4);

    // routing
    k_init<<<1, 32>>>();
    k_count<<<(NSLOT + 255) / 256, 256>>>(idx);
    k_scan<<<1, 32>>>();
    k_padinit<<<(MAXSLOT + 255) / 256, 256>>>();
    k_fill<<<(NSLOT + 255) / 256, 256>>>(idx, wts);

    // up-proj + LIF
    k_up<<<dim3(NTILE, FF / TNW), 256>>>(x, upw);

    // down-proj + LIF + combine
    k_down<<<dim3(NTILE, DD / TNW), 256>>>(dww, out);
}

// round 3
// speedup vs baseline: 1.0770x; 1.0032x over previous
#include <cuda_runtime.h>
#include <stdint.h>

// Problem constants (fixed shapes per reference)
#define TT 4
#define NN 8192
#define DD 1024
#define NE 8
#define FF 512
#define KTOP 2

#define TM 64          // tokens per tile
#define TNW 128        // f (or d) per tile
#define BK 16          // K chunk
#define NSLOT   (NN * KTOP)            // 16384
#define MAXSLOT (NSLOT + NE * TM)      // 16896 (padded)
#define NTILE   (MAXSLOT / TM)         // 264

#define BETA 0.9f
#define THRESH 1.0f

// Scratch (device globals: no allocation allowed)
__device__ float g_h[(size_t)TT * MAXSLOT * FF];   // spikes from up-proj, fp32 0/1
__device__ int   g_tok[MAXSLOT];
__device__ float g_gate[MAXSLOT];
__device__ int   g_exp[MAXSLOT];
__device__ int   g_cnt[NE];
__device__ int   g_cur[NE];
__device__ int   g_off[NE + 1];

// ---------------- f32x2 helpers ----------------

__device__ __forceinline__ unsigned long long ffma2(unsigned long long a,
                                                    unsigned long long b,
                                                    unsigned long long c) {
    unsigned long long d;
    asm("fma.rn.f32x2 %0, %1, %2, %3;" : "=l"(d) : "l"(a), "l"(b), "l"(c));
    return d;
}

__device__ __forceinline__ unsigned long long packdup(float v) {
    unsigned long long r;
    asm("mov.b64 %0, {%1, %1};" : "=l"(r) : "f"(v));
    return r;
}

__device__ __forceinline__ void unpack2(unsigned long long v, float& lo, float& hi) {
    asm("mov.b64 {%0, %1}, %2;" : "=f"(lo), "=f"(hi) : "l"(v));
}

// ---------------- routing ----------------

__global__ void k_zero(float4* out, int n4) {
    int stride = gridDim.x * blockDim.x;
    for (int i = blockIdx.x * blockDim.x + threadIdx.x; i < n4; i += stride)
        out[i] = make_float4(0.f, 0.f, 0.f, 0.f);
}

__global__ void k_init() {
    int i = threadIdx.x;
    if (i < NE) g_cnt[i] = 0;
}

__global__ void k_count(const int* __restrict__ idx) {
    int i = blockIdx.x * blockDim.x + threadIdx.x;
    if (i < NSLOT) atomicAdd(&g_cnt[idx[i]], 1);
}

__global__ void k_scan() {
    if (threadIdx.x == 0 && blockIdx.x == 0) {
        int off = 0;
        for (int e = 0; e < NE; e++) {
            g_off[e] = off;
            g_cur[e] = off;
            off += ((g_cnt[e] + TM - 1) / TM) * TM;
        }
        g_off[NE] = off;
    }
}

__global__ void k_padinit() {
    int s = blockIdx.x * blockDim.x + threadIdx.x;
    if (s < MAXSLOT) {
        g_tok[s]  = -1;
        g_gate[s] = 0.f;
        int e = 0;
        #pragma unroll
        for (int q = 0; q < NE; q++)
            if (s >= g_off[q]) e = q;
        g_exp[s] = e;
    }
}

__global__ void k_fill(const int* __restrict__ idx, const float* __restrict__ wts) {
    int i = blockIdx.x * blockDim.x + threadIdx.x;
    if (i < NSLOT) {
        int e = idx[i];
        int p = atomicAdd(&g_cur[e], 1);
        g_tok[p]  = i >> 1;     // n = i / TOPK
        g_gate[p] = wts[i];
    }
}

// ---------------- up-proj + LIF -> spikes ----------------
// grid: (NTILE, FF/TNW). Block: 256 threads. Tile: TM(64) tokens x TNW(128) f.
// Thread tile: 4 tokens (2 f32x2 pairs) x 8 f x 4 t, f32x2 packed FFMA.

__global__ __launch_bounds__(256, 1)
void k_up(const float* __restrict__ x, const float* __restrict__ upw) {
    const int sbase = blockIdx.x * TM;
    if (sbase >= g_off[NE]) return;
    const int e     = g_exp[sbase];
    const int fbase = blockIdx.y * TNW;

    __shared__ float sx[TT][BK][TM + 4];
    __shared__ float sw[BK][TNW + 4];

    const int tid = threadIdx.x;
    const int tx = tid & 15, ty = tid >> 4;
    const int tok0 = ty * 4;
    const int f0A = tx * 4;         // f columns f0A..f0A+3
    const int f0B = 64 + tx * 4;    // f columns f0B..f0B+3

    unsigned long long acc[TT][2][8];
    #pragma unroll
    for (int t = 0; t < TT; t++)
        #pragma unroll
        for (int p = 0; p < 2; p++)
            #pragma unroll
            for (int j = 0; j < 8; j++)
                acc[t][p][j] = 0ULL;

    // x loader: 256 threads -> 64 rows x 4 float4 (per t)
    const int l_row = tid >> 2;   // 0..63
    const int l_kq  = tid & 3;    // 0..3
    const int my_tok = g_tok[sbase + l_row];
    const float* xbase = x + (size_t)my_tok * DD + l_kq * 4;

    // w loader: 256 threads -> 128 rows x 2 float4
    const int w_row = tid >> 1;           // 0..127
    const int w_k   = (tid & 1) * 8;      // 0 or 8
    const float* wrow = upw + ((size_t)e * FF + (fbase + w_row)) * DD + w_k;

    for (int k0 = 0; k0 < DD; k0 += BK) {
        __syncthreads();
        #pragma unroll
        for (int t = 0; t < TT; t++) {
            float4 v = make_float4(0.f, 0.f, 0.f, 0.f);
            if (my_tok >= 0)
                v = *(const float4*)(xbase + (size_t)t * NN * DD + k0);
            sx[t][l_kq * 4 + 0][l_row] = v.x;
            sx[t][l_kq * 4 + 1][l_row] = v.y;
            sx[t][l_kq * 4 + 2][l_row] = v.z;
            sx[t][l_kq * 4 + 3][l_row] = v.w;
        }
        {
            float4 v0 = *(const float4*)(wrow + k0);
            float4 v1 = *(const float4*)(wrow + k0 + 4);
            sw[w_k + 0][w_row] = v0.x;
            sw[w_k + 1][w_row] = v0.y;
            sw[w_k + 2][w_row] = v0.z;
            sw[w_k + 3][w_row] = v0.w;
            sw[w_k + 4][w_row] = v1.x;
            sw[w_k + 5][w_row] = v1.y;
            sw[w_k + 6][w_row] = v1.z;
            sw[w_k + 7][w_row] = v1.w;
        }
        __syncthreads();

        #pragma unroll
        for (int k = 0; k < BK; k++) {
            float4 bA = *(const float4*)&sw[k][f0A];
            float4 bB = *(const float4*)&sw[k][f0B];
            unsigned long long bb[8];
            bb[0] = packdup(bA.x); bb[1] = packdup(bA.y);
            bb[2] = packdup(bA.z); bb[3] = packdup(bA.w);
            bb[4] = packdup(bB.x); bb[5] = packdup(bB.y);
            bb[6] = packdup(bB.z); bb[7] = packdup(bB.w);
            #pragma unroll
            for (int t = 0; t < TT; t++) {
                ulonglong2 av = *(const ulonglong2*)&sx[t][k][tok0];
                #pragma unroll
                for (int j = 0; j < 8; j++) {
                    acc[t][0][j] = ffma2(av.x, bb[j], acc[t][0][j]);
                    acc[t][1][j] = ffma2(av.y, bb[j], acc[t][1][j]);
                }
            }
        }
    }

    // LIF over time per (token, f), store spikes (fp32 0/1)
    #pragma unroll
    for (int p = 0; p < 2; p++) {
        #pragma unroll
        for (int l = 0; l < 2; l++) {
            const int slot = sbase + tok0 + p * 2 + l;
            float m[8];
            #pragma unroll
            for (int j = 0; j < 8; j++) m[j] = 0.f;
            #pragma unroll
            for (int t = 0; t < TT; t++) {
                float s[8];
                #pragma unroll
                for (int j = 0; j < 8; j++) {
                    float lo, hi;
                    unpack2(acc[t][p][j], lo, hi);
                    float v = l ? hi : lo;
                    m[j] = BETA * m[j] + v;
                    s[j] = (m[j] > THRESH) ? 1.f : 0.f;
                    m[j] -= s[j] * THRESH;
                }
                float* dst = &g_h[((size_t)t * MAXSLOT + slot) * FF + fbase];
                *(float4*)(dst + f0A) = make_float4(s[0], s[1], s[2], s[3]);
                *(float4*)(dst + f0B) = make_float4(s[4], s[5], s[6], s[7]);
            }
        }
    }
}

// ---------------- down-proj + LIF + gated scatter ----------------
// grid: (NTILE, DD/TNW). K = FF = 512.

__global__ __launch_bounds__(256, 1)
void k_down(const float* __restrict__ dww, float* __restrict__ out) {
    const int sbase = blockIdx.x * TM;
    if (sbase >= g_off[NE]) return;
    const int e     = g_exp[sbase];
    const int dbase = blockIdx.y * TNW;

    __shared__ float sh[TT][BK][TM + 4];
    __shared__ float sw[BK][TNW + 4];

    const int tid = threadIdx.x;
    const int tx = tid & 15, ty = tid >> 4;
    const int tok0 = ty * 4;
    const int f0A = tx * 4;
    const int f0B = 64 + tx * 4;

    unsigned long long acc[TT][2][8];
    #pragma unroll
    for (int t = 0; t < TT; t++)
        #pragma unroll
        for (int p = 0; p < 2; p++)
            #pragma unroll
            for (int j = 0; j < 8; j++)
                acc[t][p][j] = 0ULL;

    const int l_row = tid >> 2;
    const int l_kq  = tid & 3;
    const float* hbase = g_h + (size_t)(sbase + l_row) * FF + l_kq * 4;

    const int w_row = tid >> 1;
    const int w_k   = (tid & 1) * 8;
    const float* wrow = dww + ((size_t)e * DD + (dbase + w_row)) * FF + w_k;

    for (int k0 = 0; k0 < FF; k0 += BK) {
        __syncthreads();
        #pragma unroll
        for (int t = 0; t < TT; t++) {
            float4 v = *(const float4*)(hbase + (size_t)t * MAXSLOT * FF + k0);
            sh[t][l_kq * 4 + 0][l_row] = v.x;
            sh[t][l_kq * 4 + 1][l_row] = v.y;
            sh[t][l_kq * 4 + 2][l_row] = v.z;
            sh[t][l_kq * 4 + 3][l_row] = v.w;
        }
        {
            float4 v0 = *(const float4*)(wrow + k0);
            float4 v1 = *(const float4*)(wrow + k0 + 4);
            sw[w_k + 0][w_row] = v0.x;
            sw[w_k + 1][w_row] = v0.y;
            sw[w_k + 2][w_row] = v0.z;
            sw[w_k + 3][w_row] = v0.w;
            sw[w_k + 4][w_row] = v1.x;
            sw[w_k + 5][w_row] = v1.y;
            sw[w_k + 6][w_row] = v1.z;
            sw[w_k + 7][w_row] = v1.w;
        }
        __syncthreads();

        #pragma unroll
        for (int k = 0; k < BK; k++) {
            float4 bA = *(const float4*)&sw[k][f0A];
            float4 bB = *(const float4*)&sw[k][f0B];
            unsigned long long bb[8];
            bb[0] = packdup(bA.x); bb[1] = packdup(bA.y);
            bb[2] = packdup(bA.z); bb[3] = packdup(bA.w);
            bb[4] = packdup(bB.x); bb[5] = packdup(bB.y);
            bb[6] = packdup(bB.z); bb[7] = packdup(bB.w);
            #pragma unroll
            for (int t = 0; t < TT; t++) {
                ulonglong2 av = *(const ulonglong2*)&sh[t][k][tok0];
                #pragma unroll
                for (int j = 0; j < 8; j++) {
                    acc[t][0][j] = ffma2(av.x, bb[j], acc[t][0][j]);
                    acc[t][1][j] = ffma2(av.y, bb[j], acc[t][1][j]);
                }
            }
        }
    }

    // LIF over time, scatter gated spikes into out (atomic; at most 2 experts/token)
    #pragma unroll
    for (int p = 0; p < 2; p++) {
        #pragma unroll
        for (int l = 0; l < 2; l++) {
            const int slot = sbase + tok0 + p * 2 + l;
            const int tok  = g_tok[slot];
            if (tok < 0) continue;
            const float gate = g_gate[slot];
            float m[8];
            #pragma unroll
            for (int j = 0; j < 8; j++) m[j] = 0.f;
            #pragma unroll
            for (int t = 0; t < TT; t++) {
                float* op = out + ((size_t)t * NN + tok) * DD + dbase;
                #pragma unroll
                for (int j = 0; j < 8; j++) {
                    float lo, hi;
                    unpack2(acc[t][p][j], lo, hi);
                    float v = l ? hi : lo;
                    m[j] = BETA * m[j] + v;
                    if (m[j] > THRESH) {
                        m[j] -= THRESH;
                        int col = (j < 4) ? (f0A + j) : (f0B + j - 4);
                        atomicAdd(op + col, gate);
                    }
                }
            }
        }
    }
}

// ---------------- launch ----------------

extern "C" void kernel_launch(void* const* d_in, const int* in_sizes, int n_in,
                              void* d_out, int out_size) {
    const float* x    = (const float*)d_in[0];   // (T, N, D) f32
    const int*   idx  = (const int*)d_in[1];     // (N, TOPK) i32
    const float* wts  = (const float*)d_in[2];   // (N, TOPK) f32
    const float* upw  = (const float*)d_in[3];   // (E, EF, D) f32
    const float* dww  = (const float*)d_in[4];   // (E, D, EF) f32
    float* out = (float*)d_out;                  // (T, N, D) f32

    (void)in_sizes; (void)n_in; (void)out_size;

    // zero output (poisoned by harness)
    k_zero<<<4096, 256>>>((float4*)out, TT * NN * DD / 4);

    // routing
    k_init<<<1, 32>>>();
    k_count<<<(NSLOT + 255) / 256, 256>>>(idx);
    k_scan<<<1, 32>>>();
    k_padinit<<<(MAXSLOT + 255) / 256, 256>>>();
    k_fill<<<(NSLOT + 255) / 256, 256>>>(idx, wts);

    // up-proj + LIF
    k_up<<<dim3(NTILE, FF / TNW), 256>>>(x, upw);

    // down-proj + LIF + combine
    k_down<<<dim3(NTILE, DD / TNW), 256>>>(dww, out);
}

// round 5
// speedup vs baseline: 2.0071x; 1.8636x over previous
#include <cuda_runtime.h>
#include <cuda_fp16.h>
#include <stdint.h>

// ---------------- problem constants ----------------
#define TT 4
#define NN 8192
#define DD 1024
#define NE 8
#define FF 512
#define KTOP 2
#define NSLOT   (NN * KTOP)              // 16384
#define MAXSLOT (NSLOT + NE * 32)        // 16640
#define MTILES  (MAXSLOT / 32)           // 520

#define BETA 0.9f
#define THRESH 1.0f
#define LSCALE 2048.0f
#define LINV (1.0f / 2048.0f)

// smem tile: 128 rows x 32 halves, rows padded to 40 halves (80B) -> conflict-free ldmatrix
#define RPAD 40
#define TILE_B (128 * RPAD * 2)          // 10240 bytes
#define UP_SMEM  (2 * 4 * TILE_B)        // 81920
#define DN_SMEM  (2 * 3 * TILE_B)        // 61440

// ---------------- scratch ----------------
__device__ __half g_h[(size_t)MAXSLOT * 4 * FF];   // up spikes fp16 (exact 0/1), rows = slot*4+t
__device__ int   g_tok[MAXSLOT];
__device__ float g_gate[MAXSLOT];
__device__ int   g_exp[MAXSLOT];
__device__ int   g_cur[NE];
__device__ int   g_off[NE + 1];

// ---------------- helpers ----------------
__device__ __forceinline__ uint32_t smem_u32(const void* p) {
    uint32_t a;
    asm("{ .reg .u64 t; cvta.to.shared.u64 t, %1; cvt.u32.u64 %0, t; }" : "=r"(a) : "l"(p));
    return a;
}
__device__ __forceinline__ void ldsm4(uint32_t* r, uint32_t a) {
    asm volatile("ldmatrix.sync.aligned.m8n8.x4.shared.b16 {%0,%1,%2,%3}, [%4];"
        : "=r"(r[0]), "=r"(r[1]), "=r"(r[2]), "=r"(r[3]) : "r"(a));
}
__device__ __forceinline__ void mma16816(float* c, const uint32_t* a, const uint32_t* b) {
    asm volatile("mma.sync.aligned.m16n8k16.row.col.f32.f16.f16.f32 "
        "{%0,%1,%2,%3},{%4,%5,%6,%7},{%8,%9},{%0,%1,%2,%3};"
        : "+f"(c[0]), "+f"(c[1]), "+f"(c[2]), "+f"(c[3])
        : "r"(a[0]), "r"(a[1]), "r"(a[2]), "r"(a[3]), "r"(b[0]), "r"(b[1]));
}

// split 16 fp32 -> h (fp16) and l' = rn16((v-h)*2^11), packed as 8 u32 each
__device__ __forceinline__ void split16(const float* f, uint32_t* hp, uint32_t* lp) {
#pragma unroll
    for (int i = 0; i < 8; i++) {
        float f0 = f[2 * i], f1 = f[2 * i + 1];
        __half h0 = __float2half_rn(f0), h1 = __float2half_rn(f1);
        float r0 = f0 - __half2float(h0), r1 = f1 - __half2float(h1);
        __half l0 = __float2half_rn(r0 * LSCALE), l1 = __float2half_rn(r1 * LSCALE);
        __half2 hh = __halves2half2(h0, h1), ll = __halves2half2(l0, l1);
        hp[i] = *(uint32_t*)&hh;
        lp[i] = *(uint32_t*)&ll;
    }
}
__device__ __forceinline__ void sts32B(char* p, const uint32_t* v) {
    *(uint4*)p        = make_uint4(v[0], v[1], v[2], v[3]);
    *(uint4*)(p + 16) = make_uint4(v[4], v[5], v[6], v[7]);
}

// LIF across 4 timestep-lanes (stride-4 shuffle); returns this lane's own-t spikes
__device__ __forceinline__ void lif4(float v0, float v1, int srcb, int own_t,
                                     float& sp0, float& sp1) {
    float m0 = 0.f, m1 = 0.f;
    sp0 = 0.f; sp1 = 0.f;
#pragma unroll
    for (int t4 = 0; t4 < 4; t4++) {
        float u0 = __shfl_sync(0xffffffffu, v0, srcb + 4 * t4);
        float u1 = __shfl_sync(0xffffffffu, v1, srcb + 4 * t4);
        m0 = BETA * m0 + u0; float s0 = (m0 > THRESH) ? 1.f : 0.f; m0 -= s0 * THRESH;
        m1 = BETA * m1 + u1; float s1 = (m1 > THRESH) ? 1.f : 0.f; m1 -= s1 * THRESH;
        if (t4 == own_t) { sp0 = s0; sp1 = s1; }
    }
}

// ---------------- routing / zero ----------------
__global__ void k_route(const int* __restrict__ idx, const float* __restrict__ wts) {
    __shared__ int scnt[NE];
    int tid = threadIdx.x;
    if (tid < NE) scnt[tid] = 0;
    __syncthreads();
    for (int i = tid; i < NSLOT; i += 512) atomicAdd(&scnt[idx[i]], 1);
    __syncthreads();
    if (tid == 0) {
        int off = 0;
        for (int e = 0; e < NE; e++) {
            g_off[e] = off; g_cur[e] = off;
            off += (scnt[e] + 31) & ~31;
        }
        g_off[NE] = off;
    }
    __syncthreads();
    for (int s = tid; s < MAXSLOT; s += 512) {
        g_tok[s] = -1; g_gate[s] = 0.f;
        int e = 0;
#pragma unroll
        for (int q = 1; q < NE; q++) if (s >= g_off[q]) e = q;
        g_exp[s] = e;
    }
    __syncthreads();
    for (int i = tid; i < NSLOT; i += 512) {
        int e = idx[i];
        int p = atomicAdd(&g_cur[e], 1);
        g_tok[p] = i >> 1;
        g_gate[p] = wts[i];
    }
}
__global__ void k_zero(float4* out, int n4) {
    int stride = gridDim.x * blockDim.x;
    for (int i = blockIdx.x * blockDim.x + threadIdx.x; i < n4; i += stride)
        out[i] = make_float4(0.f, 0.f, 0.f, 0.f);
}

// ---------------- up compute chunk ----------------
__device__ __forceinline__ void comp_up(uint32_t bufb, int lane, int wm, int wn,
                                        float (&a1)[2][8][4], float (&a2)[2][8][4]) {
#pragma unroll
    for (int k16 = 0; k16 < 2; k16++) {
        uint32_t koff = k16 * 16 + ((lane >> 4) << 3);
        uint32_t aoff = ((wm * 32 + (lane & 15)) * RPAD + koff) * 2;
        uint32_t ah[2][4], al[2][4];
        ldsm4(ah[0], bufb + aoff);
        ldsm4(ah[1], bufb + aoff + 16 * RPAD * 2);
        ldsm4(al[0], bufb + TILE_B + aoff);
        ldsm4(al[1], bufb + TILE_B + aoff + 16 * RPAD * 2);
        uint32_t boff = ((wn * 64 + (lane & 15)) * RPAD + koff) * 2;
        uint32_t bh[8][2], bl[8][2];
#pragma unroll
        for (int g = 0; g < 4; g++) {
            uint32_t r[4];
            ldsm4(r, bufb + 2 * TILE_B + boff + g * 16 * RPAD * 2);
            bh[2 * g][0] = r[0]; bh[2 * g][1] = r[2];
            bh[2 * g + 1][0] = r[1]; bh[2 * g + 1][1] = r[3];
            ldsm4(r, bufb + 3 * TILE_B + boff + g * 16 * RPAD * 2);
            bl[2 * g][0] = r[0]; bl[2 * g][1] = r[2];
            bl[2 * g + 1][0] = r[1]; bl[2 * g + 1][1] = r[3];
        }
#pragma unroll
        for (int im = 0; im < 2; im++)
#pragma unroll
            for (int j = 0; j < 8; j++) {
                mma16816(a1[im][j], ah[im], bh[j]);
                mma16816(a2[im][j], ah[im], bl[j]);
                mma16816(a2[im][j], al[im], bh[j]);
            }
    }
}

// ---------------- up-proj + LIF -> fp16 spikes ----------------
// grid (4, MTILES), 256 threads. CTA tile 128 m (32 slots x 4t) x 128 f, K=1024.
__global__ __launch_bounds__(256, 1)
void k_up(const float* __restrict__ x, const float* __restrict__ upw) {
    const int tile_m = blockIdx.y, sbase = tile_m * 32;
    if (sbase >= g_off[NE]) return;
    const int e = g_exp[sbase];
    const int fbase = blockIdx.x * 128;

    extern __shared__ char smem[];
    const uint32_t sb = smem_u32(smem);
    const int tid = threadIdx.x, lane = tid & 31, warp = tid >> 5;
    const int wm = warp >> 1, wn = warp & 1;

    // loader: thread -> (row 0..127, k-seg 0/16)
    const int lrow = tid >> 1, lks = (tid & 1) * 16;
    int tok = g_tok[sbase + (lrow >> 2)];
    if (tok < 0) tok = 0;
    const float* aptr = x + ((size_t)(lrow & 3) * NN + tok) * DD + lks;
    const float* bptr = upw + ((size_t)e * FF + fbase + lrow) * DD + lks;
    const uint32_t sts_off = (uint32_t)(lrow * RPAD + lks) * 2;

    float a1[2][8][4], a2[2][8][4];
#pragma unroll
    for (int im = 0; im < 2; im++)
#pragma unroll
        for (int j = 0; j < 8; j++)
#pragma unroll
            for (int q = 0; q < 4; q++) { a1[im][j][q] = 0.f; a2[im][j][q] = 0.f; }

    float fA[16], fB[16];
    // prologue: load + store chunk 0
#pragma unroll
    for (int q = 0; q < 4; q++) {
        float4 v = *(const float4*)(aptr + q * 4);
        fA[4 * q] = v.x; fA[4 * q + 1] = v.y; fA[4 * q + 2] = v.z; fA[4 * q + 3] = v.w;
        float4 w = *(const float4*)(bptr + q * 4);
        fB[4 * q] = w.x; fB[4 * q + 1] = w.y; fB[4 * q + 2] = w.z; fB[4 * q + 3] = w.w;
    }
    {
        uint32_t h[8], l[8];
        split16(fA, h, l);
        sts32B(smem + sts_off, h);
        sts32B(smem + TILE_B + sts_off, l);
        split16(fB, h, l);
        sts32B(smem + 2 * TILE_B + sts_off, h);
        sts32B(smem + 3 * TILE_B + sts_off, l);
    }
    __syncthreads();

    const int NC = DD / 32;   // 32
    for (int c = 0; c < NC; c++) {
        const int buf = c & 1;
        if (c + 1 < NC) {
#pragma unroll
            for (int q = 0; q < 4; q++) {
                float4 v = *(const float4*)(aptr + (c + 1) * 32 + q * 4);
                fA[4 * q] = v.x; fA[4 * q + 1] = v.y; fA[4 * q + 2] = v.z; fA[4 * q + 3] = v.w;
                float4 w = *(const float4*)(bptr + (c + 1) * 32 + q * 4);
                fB[4 * q] = w.x; fB[4 * q + 1] = w.y; fB[4 * q + 2] = w.z; fB[4 * q + 3] = w.w;
            }
        }
        comp_up(sb + buf * 4 * TILE_B, lane, wm, wn, a1, a2);
        if (c + 1 < NC) {
            char* nb = smem + (buf ^ 1) * 4 * TILE_B;
            uint32_t h[8], l[8];
            split16(fA, h, l);
            sts32B(nb + sts_off, h);
            sts32B(nb + TILE_B + sts_off, l);
            split16(fB, h, l);
            sts32B(nb + 2 * TILE_B + sts_off, h);
            sts32B(nb + 3 * TILE_B + sts_off, l);
        }
        __syncthreads();
    }

    // epilogue: combine, LIF (stride-4 shuffles), store fp16 spikes
    const int cg = lane & 3;
    const int srcb = (lane & 16) + cg;
    const int own_t = (lane >> 2) & 3;
#pragma unroll
    for (int im = 0; im < 2; im++)
#pragma unroll
        for (int j = 0; j < 8; j++) {
            float v[4];
#pragma unroll
            for (int q = 0; q < 4; q++) v[q] = a1[im][j][q] + a2[im][j][q] * LINV;
            float sp0, sp1, sp2, sp3;
            lif4(v[0], v[1], srcb, own_t, sp0, sp1);
            lif4(v[2], v[3], srcb, own_t, sp2, sp3);
            const int mloc = wm * 32 + im * 16 + (lane >> 2);
            const int mg = tile_m * 128 + mloc;
            const int col = fbase + wn * 64 + j * 8 + 2 * cg;
            *(__half2*)(&g_h[(size_t)mg * FF + col])       = __floats2half2_rn(sp0, sp1);
            *(__half2*)(&g_h[(size_t)(mg + 8) * FF + col]) = __floats2half2_rn(sp2, sp3);
        }
}

// ---------------- down compute chunk ----------------
__device__ __forceinline__ void comp_dn(uint32_t bufb, int lane, int wm, int wn,
                                        float (&a1)[2][8][4], float (&a2)[2][8][4]) {
#pragma unroll
    for (int k16 = 0; k16 < 2; k16++) {
        uint32_t koff = k16 * 16 + ((lane >> 4) << 3);
        uint32_t aoff = ((wm * 32 + (lane & 15)) * RPAD + koff) * 2;
        uint32_t as[2][4];
        ldsm4(as[0], bufb + aoff);
        ldsm4(as[1], bufb + aoff + 16 * RPAD * 2);
        uint32_t boff = ((wn * 64 + (lane & 15)) * RPAD + koff) * 2;
        uint32_t bh[8][2], bl[8][2];
#pragma unroll
        for (int g = 0; g < 4; g++) {
            uint32_t r[4];
            ldsm4(r, bufb + 1 * TILE_B + boff + g * 16 * RPAD * 2);
            bh[2 * g][0] = r[0]; bh[2 * g][1] = r[2];
            bh[2 * g + 1][0] = r[1]; bh[2 * g + 1][1] = r[3];
            ldsm4(r, bufb + 2 * TILE_B + boff + g * 16 * RPAD * 2);
            bl[2 * g][0] = r[0]; bl[2 * g][1] = r[2];
            bl[2 * g + 1][0] = r[1]; bl[2 * g + 1][1] = r[3];
        }
#pragma unroll
        for (int im = 0; im < 2; im++)
#pragma unroll
            for (int j = 0; j < 8; j++) {
                mma16816(a1[im][j], as[im], bh[j]);
                mma16816(a2[im][j], as[im], bl[j]);
            }
    }
}

// ---------------- down-proj + LIF + gated scatter ----------------
// grid (8, MTILES), 256 threads. K = 512. A = fp16 spikes (exact), B split-2 scaled.
__global__ __launch_bounds__(256, 1)
void k_down(const float* __restrict__ dww, float* __restrict__ out) {
    const int tile_m = blockIdx.y, sbase = tile_m * 32;
    if (sbase >= g_off[NE]) return;
    const int e = g_exp[sbase];
    const int dbase = blockIdx.x * 128;

    extern __shared__ char smem[];
    const uint32_t sb = smem_u32(smem);
    const int tid = threadIdx.x, lane = tid & 31, warp = tid >> 5;
    const int wm = warp >> 1, wn = warp & 1;

    const int lrow = tid >> 1, lks = (tid & 1) * 16;
    const __half* aptr = g_h + (size_t)(tile_m * 128 + lrow) * FF + lks;
    const float* bptr = dww + ((size_t)e * DD + dbase + lrow) * FF + lks;
    const uint32_t sts_off = (uint32_t)(lrow * RPAD + lks) * 2;

    float a1[2][8][4], a2[2][8][4];
#pragma unroll
    for (int im = 0; im < 2; im++)
#pragma unroll
        for (int j = 0; j < 8; j++)
#pragma unroll
            for (int q = 0; q < 4; q++) { a1[im][j][q] = 0.f; a2[im][j][q] = 0.f; }

    uint4 rA0, rA1;
    float fB[16];
    rA0 = ((const uint4*)aptr)[0];
    rA1 = ((const uint4*)aptr)[1];
#pragma unroll
    for (int q = 0; q < 4; q++) {
        float4 w = *(const float4*)(bptr + q * 4);
        fB[4 * q] = w.x; fB[4 * q + 1] = w.y; fB[4 * q + 2] = w.z; fB[4 * q + 3] = w.w;
    }
    {
        *(uint4*)(smem + sts_off) = rA0;
        *(uint4*)(smem + sts_off + 16) = rA1;
        uint32_t h[8], l[8];
        split16(fB, h, l);
        sts32B(smem + 1 * TILE_B + sts_off, h);
        sts32B(smem + 2 * TILE_B + sts_off, l);
    }
    __syncthreads();

    const int NC = FF / 32;   // 16
    for (int c = 0; c < NC; c++) {
        const int buf = c & 1;
        if (c + 1 < NC) {
            rA0 = ((const uint4*)(aptr + (c + 1) * 32))[0];
            rA1 = ((const uint4*)(aptr + (c + 1) * 32))[1];
#pragma unroll
            for (int q = 0; q < 4; q++) {
                float4 w = *(const float4*)(bptr + (c + 1) * 32 + q * 4);
                fB[4 * q] = w.x; fB[4 * q + 1] = w.y; fB[4 * q + 2] = w.z; fB[4 * q + 3] = w.w;
            }
        }
        comp_dn(sb + buf * 3 * TILE_B, lane, wm, wn, a1, a2);
        if (c + 1 < NC) {
            char* nb = smem + (buf ^ 1) * 3 * TILE_B;
            *(uint4*)(nb + sts_off) = rA0;
            *(uint4*)(nb + sts_off + 16) = rA1;
            uint32_t h[8], l[8];
            split16(fB, h, l);
            sts32B(nb + 1 * TILE_B + sts_off, h);
            sts32B(nb + 2 * TILE_B + sts_off, l);
        }
        __syncthreads();
    }

    // epilogue: combine, LIF, gated atomic scatter
    const int cg = lane & 3;
    const int srcb = (lane & 16) + cg;
    const int own_t = (lane >> 2) & 3;
#pragma unroll
    for (int im = 0; im < 2; im++)
#pragma unroll
        for (int j = 0; j < 8; j++) {
            float v[4];
#pragma unroll
            for (int q = 0; q < 4; q++) v[q] = a1[im][j][q] + a2[im][j][q] * LINV;
            float sp0, sp1, sp2, sp3;
            lif4(v[0], v[1], srcb, own_t, sp0, sp1);
            lif4(v[2], v[3], srcb, own_t, sp2, sp3);
            const int mloc = wm * 32 + im * 16 + (lane >> 2);
            const int col = dbase + wn * 64 + j * 8 + 2 * cg;
            {
                const int slot = sbase + (mloc >> 2);
                const int tok = g_tok[slot];
                if (tok >= 0 && (sp0 != 0.f || sp1 != 0.f)) {
                    const float gate = g_gate[slot];
                    float* op = out + ((size_t)own_t * NN + tok) * DD + col;
                    if (sp0 != 0.f) atomicAdd(op, gate);
                    if (sp1 != 0.f) atomicAdd(op + 1, gate);
                }
            }
            {
                const int slot = sbase + ((mloc + 8) >> 2);
                const int tok = g_tok[slot];
                if (tok >= 0 && (sp2 != 0.f || sp3 != 0.f)) {
                    const float gate = g_gate[slot];
                    float* op = out + ((size_t)own_t * NN + tok) * DD + col;
                    if (sp2 != 0.f) atomicAdd(op, gate);
                    if (sp3 != 0.f) atomicAdd(op + 1, gate);
                }
            }
        }
}

// ---------------- launch ----------------
extern "C" void kernel_launch(void* const* d_in, const int* in_sizes, int n_in,
                              void* d_out, int out_size) {
    const float* x    = (const float*)d_in[0];
    const int*   idx  = (const int*)d_in[1];
    const float* wts  = (const float*)d_in[2];
    const float* upw  = (const float*)d_in[3];
    const float* dww  = (const float*)d_in[4];
    float* out = (float*)d_out;
    (void)in_sizes; (void)n_in; (void)out_size;

    static int smem_set = 0;
    if (!smem_set) {
        cudaFuncSetAttribute(k_up,   cudaFuncAttributeMaxDynamicSharedMemorySize, UP_SMEM);
        cudaFuncSetAttribute(k_down, cudaFuncAttributeMaxDynamicSharedMemorySize, DN_SMEM);
        smem_set = 1;
    }

    k_zero<<<4096, 256>>>((float4*)out, TT * NN * DD / 4);
    k_route<<<1, 512>>>(idx, wts);
    k_up<<<dim3(FF / 128, MTILES), 256, UP_SMEM>>>(x, upw);
    k_down<<<dim3(DD / 128, MTILES), 256, DN_SMEM>>>(dww, out);
}

// round 6
// speedup vs baseline: 2.2666x; 1.1293x over previous
#include <cuda_runtime.h>
#include <cuda_fp16.h>
#include <stdint.h>

// ---------------- problem constants ----------------
#define TT 4
#define NN 8192
#define DD 1024
#define NE 8
#define FF 512
#define KTOP 2
#define NSLOT   (NN * KTOP)              // 16384
#define MAXSLOT (NSLOT + NE * 32)        // 16640
#define MTILES  (MAXSLOT / 32)           // 520

#define BETA 0.9f
#define THRESH 1.0f
#define LSC 128.0f                        // 2^7 residual scale

// smem tiles: rows padded to 40 halves (80B) -> conflict-free ldmatrix
#define RPAD 40
#define ATB (128 * RPAD * 2)             // 10240 (128-row tile)
#define BTB (64 * RPAD * 2)              // 5120  (64-row tile)
#define UP_STRIDE (2 * ATB + 2 * BTB)    // 30720: Ah, Al, Bh, Bl
#define UP_SMEM (2 * UP_STRIDE)          // 61440
#define DN_STRIDE (ATB + 2 * BTB)        // 20480: A, Bh, Bl
#define DN_SMEM (2 * DN_STRIDE)          // 40960

// ---------------- scratch ----------------
__device__ __half g_h[(size_t)MAXSLOT * 4 * FF];   // up spikes fp16 (exact 0/1), row = slot*4+t
__device__ int   g_tok[MAXSLOT];
__device__ float g_gate[MAXSLOT];
__device__ int   g_exp[MAXSLOT];
__device__ int   g_cur[NE];
__device__ int   g_off[NE + 1];

// ---------------- helpers ----------------
__device__ __forceinline__ uint32_t smem_u32(const void* p) {
    uint32_t a;
    asm("{ .reg .u64 t; cvta.to.shared.u64 t, %1; cvt.u32.u64 %0, t; }" : "=r"(a) : "l"(p));
    return a;
}
__device__ __forceinline__ void ldsm4(uint32_t* r, uint32_t a) {
    asm volatile("ldmatrix.sync.aligned.m8n8.x4.shared.b16 {%0,%1,%2,%3}, [%4];"
        : "=r"(r[0]), "=r"(r[1]), "=r"(r[2]), "=r"(r[3]) : "r"(a));
}
__device__ __forceinline__ void mma16816(float* c, const uint32_t* a, const uint32_t* b) {
    asm volatile("mma.sync.aligned.m16n8k16.row.col.f32.f16.f16.f32 "
        "{%0,%1,%2,%3},{%4,%5,%6,%7},{%8,%9},{%0,%1,%2,%3};"
        : "+f"(c[0]), "+f"(c[1]), "+f"(c[2]), "+f"(c[3])
        : "r"(a[0]), "r"(a[1]), "r"(a[2]), "r"(a[3]), "r"(b[0]), "r"(b[1]));
}
// packed fp16 multiply by 2^-7 (exact exponent shift in normal range)
__device__ __forceinline__ uint32_t h2dn7(uint32_t a) {
    uint32_t r;
    asm("mul.f16x2 %0, %1, %2;" : "=r"(r) : "r"(a), "r"(0x20002000u));  // 0x2000 = fp16 2^-7
    return r;
}

// split fp32 -> h = rn16(v), l = rn16((v-h)*2^7)
__device__ __forceinline__ void split16(const float* f, uint32_t* hp, uint32_t* lp) {
#pragma unroll
    for (int i = 0; i < 8; i++) {
        float f0 = f[2 * i], f1 = f[2 * i + 1];
        __half h0 = __float2half_rn(f0), h1 = __float2half_rn(f1);
        __half l0 = __float2half_rn((f0 - __half2float(h0)) * LSC);
        __half l1 = __float2half_rn((f1 - __half2float(h1)) * LSC);
        __half2 hh = __halves2half2(h0, h1), ll = __halves2half2(l0, l1);
        hp[i] = *(uint32_t*)&hh;
        lp[i] = *(uint32_t*)&ll;
    }
}
__device__ __forceinline__ void split8(const float* f, uint32_t* hp, uint32_t* lp) {
#pragma unroll
    for (int i = 0; i < 4; i++) {
        float f0 = f[2 * i], f1 = f[2 * i + 1];
        __half h0 = __float2half_rn(f0), h1 = __float2half_rn(f1);
        __half l0 = __float2half_rn((f0 - __half2float(h0)) * LSC);
        __half l1 = __float2half_rn((f1 - __half2float(h1)) * LSC);
        __half2 hh = __halves2half2(h0, h1), ll = __halves2half2(l0, l1);
        hp[i] = *(uint32_t*)&hh;
        lp[i] = *(uint32_t*)&ll;
    }
}
__device__ __forceinline__ void sts32B(char* p, const uint32_t* v) {
    *(uint4*)p        = make_uint4(v[0], v[1], v[2], v[3]);
    *(uint4*)(p + 16) = make_uint4(v[4], v[5], v[6], v[7]);
}

// LIF across 4 timestep-lanes (stride-4 shuffle); returns this lane's own-t spikes
__device__ __forceinline__ void lif4(float v0, float v1, int srcb, int own_t,
                                     float& sp0, float& sp1) {
    float m0 = 0.f, m1 = 0.f;
    sp0 = 0.f; sp1 = 0.f;
#pragma unroll
    for (int t4 = 0; t4 < 4; t4++) {
        float u0 = __shfl_sync(0xffffffffu, v0, srcb + 4 * t4);
        float u1 = __shfl_sync(0xffffffffu, v1, srcb + 4 * t4);
        m0 = BETA * m0 + u0; float s0 = (m0 > THRESH) ? 1.f : 0.f; m0 -= s0 * THRESH;
        m1 = BETA * m1 + u1; float s1 = (m1 > THRESH) ? 1.f : 0.f; m1 -= s1 * THRESH;
        if (t4 == own_t) { sp0 = s0; sp1 = s1; }
    }
}

// ---------------- routing / zero ----------------
__global__ void k_route(const int* __restrict__ idx, const float* __restrict__ wts) {
    __shared__ int scnt[NE];
    int tid = threadIdx.x;
    if (tid < NE) scnt[tid] = 0;
    __syncthreads();
    for (int i = tid; i < NSLOT; i += 512) atomicAdd(&scnt[idx[i]], 1);
    __syncthreads();
    if (tid == 0) {
        int off = 0;
        for (int e = 0; e < NE; e++) {
            g_off[e] = off; g_cur[e] = off;
            off += (scnt[e] + 31) & ~31;
        }
        g_off[NE] = off;
    }
    __syncthreads();
    for (int s = tid; s < MAXSLOT; s += 512) {
        g_tok[s] = -1; g_gate[s] = 0.f;
        int e = 0;
#pragma unroll
        for (int q = 1; q < NE; q++) if (s >= g_off[q]) e = q;
        g_exp[s] = e;
    }
    __syncthreads();
    for (int i = tid; i < NSLOT; i += 512) {
        int e = idx[i];
        int p = atomicAdd(&g_cur[e], 1);
        g_tok[p] = i >> 1;
        g_gate[p] = wts[i];
    }
}
__global__ void k_zero(float4* out, int n4) {
    int stride = gridDim.x * blockDim.x;
    for (int i = blockIdx.x * blockDim.x + threadIdx.x; i < n4; i += stride)
        out[i] = make_float4(0.f, 0.f, 0.f, 0.f);
}

// ---------------- up compute chunk (warp tile 32x32, 3 MMAs, single acc) ----------------
__device__ __forceinline__ void comp_up(uint32_t bufb, int lane, int wm, int wn,
                                        float (&acc)[2][4][4]) {
#pragma unroll
    for (int k16 = 0; k16 < 2; k16++) {
        uint32_t koff = k16 * 16 + ((lane >> 4) << 3);
        uint32_t aoff = ((wm * 32 + (lane & 15)) * RPAD + koff) * 2;
        uint32_t ah[2][4], al[2][4];
        ldsm4(ah[0], bufb + aoff);
        ldsm4(ah[1], bufb + aoff + 16 * RPAD * 2);
        ldsm4(al[0], bufb + ATB + aoff);
        ldsm4(al[1], bufb + ATB + aoff + 16 * RPAD * 2);
        uint32_t boff = ((wn * 32 + (lane & 15)) * RPAD + koff) * 2;
        uint32_t bh[4][2], bl[4][2], bhs[4][2];
#pragma unroll
        for (int g = 0; g < 2; g++) {
            uint32_t r[4];
            ldsm4(r, bufb + 2 * ATB + boff + g * 16 * RPAD * 2);
            bh[2 * g][0] = r[0]; bh[2 * g][1] = r[2];
            bh[2 * g + 1][0] = r[1]; bh[2 * g + 1][1] = r[3];
            ldsm4(r, bufb + 2 * ATB + BTB + boff + g * 16 * RPAD * 2);
            bl[2 * g][0] = r[0]; bl[2 * g][1] = r[2];
            bl[2 * g + 1][0] = r[1]; bl[2 * g + 1][1] = r[3];
        }
        uint32_t ahs[2][4];
#pragma unroll
        for (int im = 0; im < 2; im++)
#pragma unroll
            for (int q = 0; q < 4; q++) ahs[im][q] = h2dn7(ah[im][q]);
#pragma unroll
        for (int j = 0; j < 4; j++) { bhs[j][0] = h2dn7(bh[j][0]); bhs[j][1] = h2dn7(bh[j][1]); }
#pragma unroll
        for (int im = 0; im < 2; im++)
#pragma unroll
            for (int j = 0; j < 4; j++) {
                mma16816(acc[im][j], ah[im], bh[j]);    // xh*wh
                mma16816(acc[im][j], ahs[im], bl[j]);   // (xh*2^-7)*(res_w*2^7)
                mma16816(acc[im][j], al[im], bhs[j]);   // (res_x*2^7)*(wh*2^-7)
            }
    }
}

// ---------------- up-proj + LIF -> fp16 spikes ----------------
// grid (FF/64=8, MTILES), 256 thr. CTA tile 128m (32 slots x 4t) x 64n, K=1024.
__global__ __launch_bounds__(256, 2)
void k_up(const float* __restrict__ x, const float* __restrict__ upw) {
    const int tile_m = blockIdx.y, sbase = tile_m * 32;
    if (sbase >= g_off[NE]) return;
    const int e = g_exp[sbase];
    const int fbase = blockIdx.x * 64;

    extern __shared__ char smem[];
    const uint32_t sb = smem_u32(smem);
    const int tid = threadIdx.x, lane = tid & 31, warp = tid >> 5;
    const int wm = warp >> 1, wn = warp & 1;

    // A loader: 2 threads/row, 16 floats each
    const int lrowA = tid >> 1, lksA = (tid & 1) * 16;
    int tok = g_tok[sbase + (lrowA >> 2)];
    if (tok < 0) tok = 0;
    const float* aptr = x + ((size_t)(lrowA & 3) * NN + tok) * DD + lksA;
    const uint32_t stsA = (uint32_t)(lrowA * RPAD + lksA) * 2;
    // B loader: 4 threads/row, 8 floats each
    const int lrowB = tid >> 2, lqB = (tid & 3) * 8;
    const float* bptr = upw + ((size_t)e * FF + fbase + lrowB) * DD + lqB;
    const uint32_t stsB = (uint32_t)(lrowB * RPAD + lqB) * 2;

    float acc[2][4][4];
#pragma unroll
    for (int im = 0; im < 2; im++)
#pragma unroll
        for (int j = 0; j < 4; j++)
#pragma unroll
            for (int q = 0; q < 4; q++) acc[im][j][q] = 0.f;

    float fA[16], fB[8];
#pragma unroll
    for (int q = 0; q < 4; q++) {
        float4 v = *(const float4*)(aptr + q * 4);
        fA[4 * q] = v.x; fA[4 * q + 1] = v.y; fA[4 * q + 2] = v.z; fA[4 * q + 3] = v.w;
    }
#pragma unroll
    for (int q = 0; q < 2; q++) {
        float4 w = *(const float4*)(bptr + q * 4);
        fB[4 * q] = w.x; fB[4 * q + 1] = w.y; fB[4 * q + 2] = w.z; fB[4 * q + 3] = w.w;
    }
    {
        uint32_t h[8], l[8];
        split16(fA, h, l);
        sts32B(smem + stsA, h);
        sts32B(smem + ATB + stsA, l);
        uint32_t hb[4], lb[4];
        split8(fB, hb, lb);
        *(uint4*)(smem + 2 * ATB + stsB) = make_uint4(hb[0], hb[1], hb[2], hb[3]);
        *(uint4*)(smem + 2 * ATB + BTB + stsB) = make_uint4(lb[0], lb[1], lb[2], lb[3]);
    }
    __syncthreads();

    const int NC = DD / 32;   // 32
    for (int c = 0; c < NC; c++) {
        const int buf = c & 1;
        if (c + 1 < NC) {
#pragma unroll
            for (int q = 0; q < 4; q++) {
                float4 v = *(const float4*)(aptr + (c + 1) * 32 + q * 4);
                fA[4 * q] = v.x; fA[4 * q + 1] = v.y; fA[4 * q + 2] = v.z; fA[4 * q + 3] = v.w;
            }
#pragma unroll
            for (int q = 0; q < 2; q++) {
                float4 w = *(const float4*)(bptr + (c + 1) * 32 + q * 4);
                fB[4 * q] = w.x; fB[4 * q + 1] = w.y; fB[4 * q + 2] = w.z; fB[4 * q + 3] = w.w;
            }
        }
        comp_up(sb + buf * UP_STRIDE, lane, wm, wn, acc);
        if (c + 1 < NC) {
            char* nb = smem + (buf ^ 1) * UP_STRIDE;
            uint32_t h[8], l[8];
            split16(fA, h, l);
            sts32B(nb + stsA, h);
            sts32B(nb + ATB + stsA, l);
            uint32_t hb[4], lb[4];
            split8(fB, hb, lb);
            *(uint4*)(nb + 2 * ATB + stsB) = make_uint4(hb[0], hb[1], hb[2], hb[3]);
            *(uint4*)(nb + 2 * ATB + BTB + stsB) = make_uint4(lb[0], lb[1], lb[2], lb[3]);
        }
        __syncthreads();
    }

    // epilogue: LIF (stride-4 shuffles), store fp16 spikes
    const int cg = lane & 3;
    const int srcb = (lane & 16) + cg;
    const int own_t = (lane >> 2) & 3;
#pragma unroll
    for (int im = 0; im < 2; im++)
#pragma unroll
        for (int j = 0; j < 4; j++) {
            float sp0, sp1, sp2, sp3;
            lif4(acc[im][j][0], acc[im][j][1], srcb, own_t, sp0, sp1);
            lif4(acc[im][j][2], acc[im][j][3], srcb, own_t, sp2, sp3);
            const int mloc = wm * 32 + im * 16 + (lane >> 2);
            const int mg = tile_m * 128 + mloc;
            const int col = fbase + wn * 32 + j * 8 + 2 * cg;
            *(__half2*)(&g_h[(size_t)mg * FF + col])       = __floats2half2_rn(sp0, sp1);
            *(__half2*)(&g_h[(size_t)(mg + 8) * FF + col]) = __floats2half2_rn(sp2, sp3);
        }
}

// ---------------- down compute chunk (warp tile 32x32, 2 MMAs, single acc) ----------------
__device__ __forceinline__ void comp_dn(uint32_t bufb, int lane, int wm, int wn,
                                        float (&acc)[2][4][4]) {
#pragma unroll
    for (int k16 = 0; k16 < 2; k16++) {
        uint32_t koff = k16 * 16 + ((lane >> 4) << 3);
        uint32_t aoff = ((wm * 32 + (lane & 15)) * RPAD + koff) * 2;
        uint32_t as_[2][4], ass[2][4];
        ldsm4(as_[0], bufb + aoff);
        ldsm4(as_[1], bufb + aoff + 16 * RPAD * 2);
        uint32_t boff = ((wn * 32 + (lane & 15)) * RPAD + koff) * 2;
        uint32_t bh[4][2], bl[4][2];
#pragma unroll
        for (int g = 0; g < 2; g++) {
            uint32_t r[4];
            ldsm4(r, bufb + ATB + boff + g * 16 * RPAD * 2);
            bh[2 * g][0] = r[0]; bh[2 * g][1] = r[2];
            bh[2 * g + 1][0] = r[1]; bh[2 * g + 1][1] = r[3];
            ldsm4(r, bufb + ATB + BTB + boff + g * 16 * RPAD * 2);
            bl[2 * g][0] = r[0]; bl[2 * g][1] = r[2];
            bl[2 * g + 1][0] = r[1]; bl[2 * g + 1][1] = r[3];
        }
#pragma unroll
        for (int im = 0; im < 2; im++)
#pragma unroll
            for (int q = 0; q < 4; q++) ass[im][q] = h2dn7(as_[im][q]);
#pragma unroll
        for (int im = 0; im < 2; im++)
#pragma unroll
            for (int j = 0; j < 4; j++) {
                mma16816(acc[im][j], as_[im], bh[j]);   // s*wh
                mma16816(acc[im][j], ass[im], bl[j]);   // (s*2^-7)*(res_w*2^7)
            }
    }
}

// ---------------- down-proj + LIF + gated scatter ----------------
// grid (DD/64=16, MTILES), 256 thr. K = 512. A = fp16 spikes (exact), B split.
__global__ __launch_bounds__(256, 2)
void k_down(const float* __restrict__ dww, float* __restrict__ out) {
    const int tile_m = blockIdx.y, sbase = tile_m * 32;
    if (sbase >= g_off[NE]) return;
    const int e = g_exp[sbase];
    const int dbase = blockIdx.x * 64;

    extern __shared__ char smem[];
    const uint32_t sb = smem_u32(smem);
    const int tid = threadIdx.x, lane = tid & 31, warp = tid >> 5;
    const int wm = warp >> 1, wn = warp & 1;

    const int lrowA = tid >> 1, lksA = (tid & 1) * 16;
    const __half* aptr = g_h + (size_t)(tile_m * 128 + lrowA) * FF + lksA;
    const uint32_t stsA = (uint32_t)(lrowA * RPAD + lksA) * 2;
    const int lrowB = tid >> 2, lqB = (tid & 3) * 8;
    const float* bptr = dww + ((size_t)e * DD + dbase + lrowB) * FF + lqB;
    const uint32_t stsB = (uint32_t)(lrowB * RPAD + lqB) * 2;

    float acc[2][4][4];
#pragma unroll
    for (int im = 0; im < 2; im++)
#pragma unroll
        for (int j = 0; j < 4; j++)
#pragma unroll
            for (int q = 0; q < 4; q++) acc[im][j][q] = 0.f;

    uint4 rA0 = ((const uint4*)aptr)[0];
    uint4 rA1 = ((const uint4*)aptr)[1];
    float fB[8];
#pragma unroll
    for (int q = 0; q < 2; q++) {
        float4 w = *(const float4*)(bptr + q * 4);
        fB[4 * q] = w.x; fB[4 * q + 1] = w.y; fB[4 * q + 2] = w.z; fB[4 * q + 3] = w.w;
    }
    {
        *(uint4*)(smem + stsA) = rA0;
        *(uint4*)(smem + stsA + 16) = rA1;
        uint32_t hb[4], lb[4];
        split8(fB, hb, lb);
        *(uint4*)(smem + ATB + stsB) = make_uint4(hb[0], hb[1], hb[2], hb[3]);
        *(uint4*)(smem + ATB + BTB + stsB) = make_uint4(lb[0], lb[1], lb[2], lb[3]);
    }
    __syncthreads();

    const int NC = FF / 32;   // 16
    for (int c = 0; c < NC; c++) {
        const int buf = c & 1;
        if (c + 1 < NC) {
            rA0 = ((const uint4*)(aptr + (c + 1) * 32))[0];
            rA1 = ((const uint4*)(aptr + (c + 1) * 32))[1];
#pragma unroll
            for (int q = 0; q < 2; q++) {
                float4 w = *(const float4*)(bptr + (c + 1) * 32 + q * 4);
                fB[4 * q] = w.x; fB[4 * q + 1] = w.y; fB[4 * q + 2] = w.z; fB[4 * q + 3] = w.w;
            }
        }
        comp_dn(sb + buf * DN_STRIDE, lane, wm, wn, acc);
        if (c + 1 < NC) {
            char* nb = smem + (buf ^ 1) * DN_STRIDE;
            *(uint4*)(nb + stsA) = rA0;
            *(uint4*)(nb + stsA + 16) = rA1;
            uint32_t hb[4], lb[4];
            split8(fB, hb, lb);
            *(uint4*)(nb + ATB + stsB) = make_uint4(hb[0], hb[1], hb[2], hb[3]);
            *(uint4*)(nb + ATB + BTB + stsB) = make_uint4(lb[0], lb[1], lb[2], lb[3]);
        }
        __syncthreads();
    }

    // epilogue: LIF + gated atomic scatter
    const int cg = lane & 3;
    const int srcb = (lane & 16) + cg;
    const int own_t = (lane >> 2) & 3;
#pragma unroll
    for (int im = 0; im < 2; im++)
#pragma unroll
        for (int j = 0; j < 4; j++) {
            float sp0, sp1, sp2, sp3;
            lif4(acc[im][j][0], acc[im][j][1], srcb, own_t, sp0, sp1);
            lif4(acc[im][j][2], acc[im][j][3], srcb, own_t, sp2, sp3);
            const int mloc = wm * 32 + im * 16 + (lane >> 2);
            const int col = dbase + wn * 32 + j * 8 + 2 * cg;
            {
                const int slot = sbase + (mloc >> 2);
                const int tok = g_tok[slot];
                if (tok >= 0 && (sp0 != 0.f || sp1 != 0.f)) {
                    const float gate = g_gate[slot];
                    float* op = out + ((size_t)own_t * NN + tok) * DD + col;
                    if (sp0 != 0.f) atomicAdd(op, gate);
                    if (sp1 != 0.f) atomicAdd(op + 1, gate);
                }
            }
            {
                const int slot = sbase + ((mloc + 8) >> 2);
                const int tok = g_tok[slot];
                if (tok >= 0 && (sp2 != 0.f || sp3 != 0.f)) {
                    const float gate = g_gate[slot];
                    float* op = out + ((size_t)own_t * NN + tok) * DD + col;
                    if (sp2 != 0.f) atomicAdd(op, gate);
                    if (sp3 != 0.f) atomicAdd(op + 1, gate);
                }
            }
        }
}

// ---------------- launch ----------------
extern "C" void kernel_launch(void* const* d_in, const int* in_sizes, int n_in,
                              void* d_out, int out_size) {
    const float* x    = (const float*)d_in[0];
    const int*   idx  = (const int*)d_in[1];
    const float* wts  = (const float*)d_in[2];
    const float* upw  = (const float*)d_in[3];
    const float* dww  = (const float*)d_in[4];
    float* out = (float*)d_out;
    (void)in_sizes; (void)n_in; (void)out_size;

    static int smem_set = 0;
    if (!smem_set) {
        cudaFuncSetAttribute(k_up,   cudaFuncAttributeMaxDynamicSharedMemorySize, UP_SMEM);
        cudaFuncSetAttribute(k_down, cudaFuncAttributeMaxDynamicSharedMemorySize, DN_SMEM);
        smem_set = 1;
    }

    k_zero<<<4096, 256>>>((float4*)out, TT * NN * DD / 4);
    k_route<<<1, 512>>>(idx, wts);
    k_up<<<dim3(FF / 64, MTILES), 256, UP_SMEM>>>(x, upw);
    k_down<<<dim3(DD / 64, MTILES), 256, DN_SMEM>>>(dww, out);
}